// round 7
// baseline (speedup 1.0000x reference)
#include <cuda_runtime.h>
#include <math_constants.h>
#include <cstdint>

#define DMODEL 1024
#define SEQ    2048
#define BATCH  2
#define MROWS  (BATCH * SEQ)
#define NHEADS 16
#define DK     64

// Scratch (allocation-free rule: __device__ globals)
__device__ float g_qp[MROWS * DMODEL];
__device__ float g_kp[MROWS * DMODEL];
__device__ float g_vp[MROWS * DMODEL];
__device__ float g_ao[MROWS * DMODEL];

// ===========================================================================
// PTX helpers (baseline compute_103-safe: mma.sync + cp.async only)
// ===========================================================================
__device__ __forceinline__ uint32_t smem_u32(const void* p) {
    uint32_t a;
    asm("{ .reg .u64 t; cvta.to.shared.u64 t, %1; cvt.u32.u64 %0, t; }"
        : "=r"(a) : "l"(p));
    return a;
}
#define CP_ASYNC16(smem, gptr)                                                 \
    asm volatile("cp.async.cg.shared.global [%0], [%1], 16;"                   \
                 :: "r"(smem), "l"(gptr))
#define CP_COMMIT() asm volatile("cp.async.commit_group;" ::: "memory")
#define CP_WAIT(n)  asm volatile("cp.async.wait_group %0;" :: "n"(n) : "memory")

__device__ __forceinline__ uint32_t f2tf32(float x) {
    uint32_t u;
    asm("cvt.rna.tf32.f32 %0, %1;" : "=r"(u) : "f"(x));
    return u;
}
__device__ __forceinline__ void mma_tf32(float& c0, float& c1, float& c2, float& c3,
                                         uint32_t a0, uint32_t a1, uint32_t a2, uint32_t a3,
                                         uint32_t b0, uint32_t b1) {
    asm volatile(
        "mma.sync.aligned.m16n8k8.row.col.f32.tf32.tf32.f32 "
        "{%0,%1,%2,%3}, {%4,%5,%6,%7}, {%8,%9}, {%0,%1,%2,%3};"
        : "+f"(c0), "+f"(c1), "+f"(c2), "+f"(c3)
        : "r"(a0), "r"(a1), "r"(a2), "r"(a3), "r"(b0), "r"(b1));
}

// Fast exp2: magic-number round-to-nearest + Taylor-6 on [-0.5, 0.5].
__device__ __forceinline__ float exp2m(float z) {
    z = fmaxf(z, -126.0f);
    float r = z + 12582912.0f;
    int   n = __float_as_int(r) - 0x4B400000;
    float f = z - (r - 12582912.0f);
    float p =              1.54035303933816e-4f;
    p = fmaf(p, f, 1.33335581464284e-3f);
    p = fmaf(p, f, 9.61812910762848e-3f);
    p = fmaf(p, f, 5.55041086648216e-2f);
    p = fmaf(p, f, 2.40226506959101e-1f);
    p = fmaf(p, f, 6.93147180559945e-1f);
    p = fmaf(p, f, 1.0f);
    return __int_as_float(__float_as_int(p) + (n << 23));
}
#define LOG2E 1.4426950408889634f

// ===========================================================================
// tf32 mma.sync GEMM (the proven R5 kernel):
// C[M,1024] = A[M,1024] @ W[1024,1024]^T + bias
// 128x128 CTA tile, BK=32, 256 threads, double-buffered cp.async.
// ===========================================================================
struct GemmJob { const float* A; const float* W; const float* bias; float* C; };
struct GemmParams { GemmJob job[3]; };

#define GBM 128
#define GBN 128
#define GBK 32
#define GNIT (DMODEL / GBK)
#define LDT 36
#define TILEF (128 * LDT)
#define SMEM_REQ (4 * TILEF * 4)

__global__ __launch_bounds__(256) void gemm_tf32(GemmParams p)
{
    extern __shared__ float dsm[];
    float* As = dsm;
    float* Bs = dsm + 2 * TILEF;
    const uint32_t sa = smem_u32(dsm);

    const GemmJob j = p.job[blockIdx.z];
    const int bm = blockIdx.y * GBM;
    const int bn = blockIdx.x * GBN;
    const int tid = threadIdx.x;
    const int wid = tid >> 5;
    const int lid = tid & 31;
    const int wm = (wid >> 2) * 64;
    const int wn = (wid & 3) * 32;
    const int g = lid >> 2;
    const int t = lid & 3;

    const int row0 = tid >> 3;
    const int c4 = (tid & 7) * 4;
    const float* Ag[4];
    const float* Wg[4];
    uint32_t sAoff[4], sBoff[4];
#pragma unroll
    for (int jj = 0; jj < 4; jj++) {
        int row = row0 + jj * 32;
        Ag[jj] = j.A + (size_t)(bm + row) * DMODEL + c4;
        Wg[jj] = j.W + (size_t)(bn + row) * DMODEL + c4;
        sAoff[jj] = (uint32_t)((row * LDT + c4) * 4);
        sBoff[jj] = (uint32_t)((2 * TILEF + row * LDT + c4) * 4);
    }

#pragma unroll
    for (int jj = 0; jj < 4; jj++) {
        CP_ASYNC16(sa + sAoff[jj], Ag[jj]);
        CP_ASYNC16(sa + sBoff[jj], Wg[jj]);
    }
    CP_COMMIT();

    float acc[4][4][4];
#pragma unroll
    for (int mt = 0; mt < 4; mt++)
#pragma unroll
        for (int nt = 0; nt < 4; nt++)
#pragma unroll
            for (int r = 0; r < 4; r++) acc[mt][nt][r] = 0.f;

    for (int it = 0; it < GNIT; it++) {
        CP_WAIT(0);
        __syncthreads();

        if (it + 1 < GNIT) {
            const uint32_t dst = (uint32_t)(((it + 1) & 1) * TILEF * 4);
            const int koff = (it + 1) * GBK;
#pragma unroll
            for (int jj = 0; jj < 4; jj++) {
                CP_ASYNC16(sa + sAoff[jj] + dst, Ag[jj] + koff);
                CP_ASYNC16(sa + sBoff[jj] + dst, Wg[jj] + koff);
            }
            CP_COMMIT();
        }

        const float* Ab = As + (it & 1) * TILEF;
        const float* Bb = Bs + (it & 1) * TILEF;

#pragma unroll
        for (int ks = 0; ks < 4; ks++) {
            const int kb = ks * 8;
            uint32_t bf[4][2];
#pragma unroll
            for (int nt = 0; nt < 4; nt++) {
                const float* bp = Bb + (wn + nt * 8 + g) * LDT + kb + t;
                bf[nt][0] = f2tf32(bp[0]);
                bf[nt][1] = f2tf32(bp[4]);
            }
#pragma unroll
            for (int mt = 0; mt < 4; mt++) {
                const float* ap = Ab + (wm + mt * 16 + g) * LDT + kb + t;
                uint32_t a0 = f2tf32(ap[0]);
                uint32_t a1 = f2tf32(ap[8 * LDT]);
                uint32_t a2 = f2tf32(ap[4]);
                uint32_t a3 = f2tf32(ap[8 * LDT + 4]);
#pragma unroll
                for (int nt = 0; nt < 4; nt++)
                    mma_tf32(acc[mt][nt][0], acc[mt][nt][1],
                             acc[mt][nt][2], acc[mt][nt][3],
                             a0, a1, a2, a3, bf[nt][0], bf[nt][1]);
            }
        }
        __syncthreads();
    }

#pragma unroll
    for (int mt = 0; mt < 4; mt++) {
        const int row = bm + wm + mt * 16 + g;
#pragma unroll
        for (int nt = 0; nt < 4; nt++) {
            const int col = bn + wn + nt * 8 + 2 * t;
            const float b0 = j.bias[col], b1 = j.bias[col + 1];
            float* c0p = j.C + (size_t)row * DMODEL + col;
            float* c1p = j.C + (size_t)(row + 8) * DMODEL + col;
            *(float2*)c0p = make_float2(acc[mt][nt][0] + b0, acc[mt][nt][1] + b1);
            *(float2*)c1p = make_float2(acc[mt][nt][2] + b0, acc[mt][nt][3] + b1);
        }
    }
}

// ===========================================================================
// Tensor-core flash attention v4:
//  - QK^T: single-pass tf32 (q rna, k rna)
//  - PV: single-pass tf32 — tf32-rounded P IS the weight definition;
//    l accumulates the rounded p, so output = sum p'v / sum p' (consistent)
//  - cp.async double-buffered K/V, warp-local softmax, FMA exp2
// grid (SEQ/64, H, B), 128 threads = 4 warps; warp w owns query rows 16w..16w+15.
// ===========================================================================
#define ALD 68
#define VLD 72
#define KBUF 4352
#define VBUF 4608
#define OFF_V  (2 * KBUF)
#define OFF_PB (2 * KBUF + 2 * VBUF)      // 17920
#define OFF_ST (OFF_PB + KBUF)            // 22272
#define ATT_SMEMF (OFF_ST + 192)
#define ATT_SMEMB (ATT_SMEMF * 4)

__global__ __launch_bounds__(128) void attn_mma()
{
    extern __shared__ float sm[];
    float* Pb   = sm + OFF_PB;
    float* mrow = sm + OFF_ST;
    float* lrow = sm + OFF_ST + 64;
    float* crow = sm + OFF_ST + 128;
    const uint32_t s0 = smem_u32(sm);

    const int tid = threadIdx.x;
    const int wid = tid >> 5;
    const int lid = tid & 31;
    const int g = lid >> 2;
    const int t = lid & 3;
    const int m0 = wid * 16;
    const int h = blockIdx.y;
    const int b = blockIdx.z;
    const int qbase = b * SEQ + blockIdx.x * 64;

    const float* qg = g_qp + (size_t)qbase * DMODEL + h * DK;
    const float* kg = g_kp + (size_t)b * SEQ * DMODEL + h * DK;
    const float* vg = g_vp + (size_t)b * SEQ * DMODEL + h * DK;

    const int rr = tid >> 4;
    const int cc = (tid & 15) << 2;

    // prefetch tile 0
#pragma unroll
    for (int i = 0; i < 8; i++) {
        int r = rr + i * 8;
        CP_ASYNC16(s0 + (uint32_t)((r * ALD + cc) * 4),
                   kg + (size_t)r * DMODEL + cc);
        CP_ASYNC16(s0 + (uint32_t)((OFF_V + r * VLD + cc) * 4),
                   vg + (size_t)r * DMODEL + cc);
    }
    CP_COMMIT();

    // stage Q into Pb, init stats
#pragma unroll
    for (int i = 0; i < 8; i++) {
        int r = rr + i * 8;
        *(float4*)&Pb[r * ALD + cc] = *(const float4*)(qg + (size_t)r * DMODEL + cc);
    }
    if (tid < 64) { mrow[tid] = -1e30f; lrow[tid] = 0.f; }
    __syncthreads();

    // preload scaled Q fragments (single-term, rna)
    uint32_t qb[8][4];
#pragma unroll
    for (int ks = 0; ks < 8; ks++) {
        int kb = ks * 8;
        qb[ks][0] = f2tf32(Pb[(m0 + g) * ALD + kb + t] * 0.125f);
        qb[ks][1] = f2tf32(Pb[(m0 + g + 8) * ALD + kb + t] * 0.125f);
        qb[ks][2] = f2tf32(Pb[(m0 + g) * ALD + kb + t + 4] * 0.125f);
        qb[ks][3] = f2tf32(Pb[(m0 + g + 8) * ALD + kb + t + 4] * 0.125f);
    }

    float Oa[8][4];
#pragma unroll
    for (int nt = 0; nt < 8; nt++)
#pragma unroll
        for (int r = 0; r < 4; r++) Oa[nt][r] = 0.f;

    const int NT = SEQ / 64;
    for (int tt = 0; tt < NT; tt++) {
        if (tt + 1 < NT) {
            const int buf = (tt + 1) & 1;
            const size_t gof = (size_t)(tt + 1) * 64 * DMODEL;
#pragma unroll
            for (int i = 0; i < 8; i++) {
                int r = rr + i * 8;
                CP_ASYNC16(s0 + (uint32_t)((buf * KBUF + r * ALD + cc) * 4),
                           kg + gof + (size_t)r * DMODEL + cc);
                CP_ASYNC16(s0 + (uint32_t)((OFF_V + buf * VBUF + r * VLD + cc) * 4),
                           vg + gof + (size_t)r * DMODEL + cc);
            }
            CP_COMMIT();
            CP_WAIT(1);
        } else {
            CP_WAIT(0);
        }
        __syncthreads();

        const float* Kc = sm + (tt & 1) * KBUF;
        const float* Vc = sm + OFF_V + (tt & 1) * VBUF;

        // ---- QK^T single-pass ----
        float Sa[8][4];
#pragma unroll
        for (int nt = 0; nt < 8; nt++)
#pragma unroll
            for (int r = 0; r < 4; r++) Sa[nt][r] = 0.f;

#pragma unroll
        for (int ks = 0; ks < 8; ks++) {
            int kb = ks * 8;
#pragma unroll
            for (int nt = 0; nt < 8; nt++) {
                const float* bp = Kc + (nt * 8 + g) * ALD + kb + t;
                uint32_t bb0 = f2tf32(bp[0]);
                uint32_t bb1 = f2tf32(bp[4]);
                mma_tf32(Sa[nt][0], Sa[nt][1], Sa[nt][2], Sa[nt][3],
                         qb[ks][0], qb[ks][1], qb[ks][2], qb[ks][3], bb0, bb1);
            }
        }
#pragma unroll
        for (int nt = 0; nt < 8; nt++) {
            int ccol = nt * 8 + 2 * t;
            *(float2*)&Pb[(m0 + g) * ALD + ccol]     = make_float2(Sa[nt][0], Sa[nt][1]);
            *(float2*)&Pb[(m0 + g + 8) * ALD + ccol] = make_float2(Sa[nt][2], Sa[nt][3]);
        }
        __syncwarp();

        // ---- online softmax (warp-local rows, 2 threads/row) ----
        // Store tf32-rounded p; accumulate l from the ROUNDED values so the
        // final normalization exactly matches the PV numerator weights.
        {
            int row = tid >> 1, half = tid & 1;
            float* Sr = Pb + row * ALD + half * 32;
            float4 s4[8];
            float mx = -1e30f;
#pragma unroll
            for (int i = 0; i < 8; i++) {
                s4[i] = ((float4*)Sr)[i];
                mx = fmaxf(mx, fmaxf(fmaxf(s4[i].x, s4[i].y), fmaxf(s4[i].z, s4[i].w)));
            }
            mx = fmaxf(mx, __shfl_xor_sync(0xffffffffu, mx, 1));
            float mold = mrow[row];
            float mnew = fmaxf(mold, mx);
            float ls = 0.f;
#pragma unroll
            for (int i = 0; i < 8; i++) {
                float px = __uint_as_float(f2tf32(exp2m((s4[i].x - mnew) * LOG2E)));
                float py = __uint_as_float(f2tf32(exp2m((s4[i].y - mnew) * LOG2E)));
                float pz = __uint_as_float(f2tf32(exp2m((s4[i].z - mnew) * LOG2E)));
                float pw = __uint_as_float(f2tf32(exp2m((s4[i].w - mnew) * LOG2E)));
                ls += (px + py) + (pz + pw);
                ((float4*)Sr)[i] = make_float4(px, py, pz, pw);
            }
            ls += __shfl_xor_sync(0xffffffffu, ls, 1);
            if (half == 0) {
                float cf = exp2m((mold - mnew) * LOG2E);
                mrow[row] = mnew;
                lrow[row] = lrow[row] * cf + ls;
                crow[row] = cf;
            }
        }
        __syncwarp();

        // ---- rescale O, then O += p'*vb (single-pass) ----
        {
            float c0 = crow[m0 + g], c1 = crow[m0 + g + 8];
#pragma unroll
            for (int nt = 0; nt < 8; nt++) {
                Oa[nt][0] *= c0; Oa[nt][1] *= c0;
                Oa[nt][2] *= c1; Oa[nt][3] *= c1;
            }
        }
#pragma unroll
        for (int ks = 0; ks < 8; ks++) {
            int kb = ks * 8;
            uint32_t pb0 = __float_as_uint(Pb[(m0 + g) * ALD + kb + t]);
            uint32_t pb1 = __float_as_uint(Pb[(m0 + g + 8) * ALD + kb + t]);
            uint32_t pb2 = __float_as_uint(Pb[(m0 + g) * ALD + kb + t + 4]);
            uint32_t pb3 = __float_as_uint(Pb[(m0 + g + 8) * ALD + kb + t + 4]);
#pragma unroll
            for (int nt = 0; nt < 8; nt++) {
                uint32_t vb0 = f2tf32(Vc[(kb + t) * VLD + nt * 8 + g]);
                uint32_t vb1 = f2tf32(Vc[(kb + t + 4) * VLD + nt * 8 + g]);
                mma_tf32(Oa[nt][0], Oa[nt][1], Oa[nt][2], Oa[nt][3],
                         pb0, pb1, pb2, pb3, vb0, vb1);
            }
        }
        __syncthreads();
    }

    // epilogue
    float inv0 = 1.0f / lrow[m0 + g];
    float inv1 = 1.0f / lrow[m0 + g + 8];
    float* o0 = g_ao + (size_t)(qbase + m0 + g) * DMODEL + h * DK;
    float* o1 = g_ao + (size_t)(qbase + m0 + g + 8) * DMODEL + h * DK;
#pragma unroll
    for (int nt = 0; nt < 8; nt++) {
        int ccol = nt * 8 + 2 * t;
        *(float2*)(o0 + ccol) = make_float2(Oa[nt][0] * inv0, Oa[nt][1] * inv0);
        *(float2*)(o1 + ccol) = make_float2(Oa[nt][2] * inv1, Oa[nt][3] * inv1);
    }
}

// ===========================================================================
extern "C" void kernel_launch(void* const* d_in, const int* in_sizes, int n_in,
                              void* d_out, int out_size)
{
    const float* v  = (const float*)d_in[0];
    const float* k  = (const float*)d_in[1];
    const float* q  = (const float*)d_in[2];
    const float* Wv = (const float*)d_in[3];
    const float* bv = (const float*)d_in[4];
    const float* Wk = (const float*)d_in[5];
    const float* bk = (const float*)d_in[6];
    const float* Wq = (const float*)d_in[7];
    const float* bq = (const float*)d_in[8];
    const float* Wo = (const float*)d_in[9];
    const float* bo = (const float*)d_in[10];
    float* out = (float*)d_out;

    float *qp, *kp, *vp, *ao;
    cudaGetSymbolAddress((void**)&qp, g_qp);
    cudaGetSymbolAddress((void**)&kp, g_kp);
    cudaGetSymbolAddress((void**)&vp, g_vp);
    cudaGetSymbolAddress((void**)&ao, g_ao);

    static bool attr_set = false;
    if (!attr_set) {
        cudaFuncSetAttribute(gemm_tf32,
                             cudaFuncAttributeMaxDynamicSharedMemorySize, SMEM_REQ);
        cudaFuncSetAttribute(attn_mma,
                             cudaFuncAttributeMaxDynamicSharedMemorySize, ATT_SMEMB);
        attr_set = true;
    }

    GemmParams pin;
    pin.job[0] = { q, Wq, bq, qp };
    pin.job[1] = { k, Wk, bk, kp };
    pin.job[2] = { v, Wv, bv, vp };
    dim3 ggrid(DMODEL / GBN, MROWS / GBM, 3);   // (8, 32, 3)
    gemm_tf32<<<ggrid, 256, SMEM_REQ>>>(pin);

    dim3 attn_grid(SEQ / 64, NHEADS, BATCH);    // (32, 16, 2)
    attn_mma<<<attn_grid, 128, ATT_SMEMB>>>();

    GemmParams pout;
    pout.job[0] = { ao, Wo, bo, out };
    pout.job[1] = { ao, Wo, bo, out };
    pout.job[2] = { ao, Wo, bo, out };
    dim3 ogrid(DMODEL / GBN, MROWS / GBM, 1);   // (8, 32, 1)
    gemm_tf32<<<ogrid, 256, SMEM_REQ>>>(pout);
}

// round 8
// speedup vs baseline: 1.3718x; 1.3718x over previous
#include <cuda_runtime.h>
#include <math_constants.h>
#include <cstdint>

#define DMODEL 1024
#define SEQ    2048
#define BATCH  2
#define MROWS  (BATCH * SEQ)
#define NHEADS 16
#define DK     64

// Scratch (allocation-free rule: __device__ globals)
__device__ float g_qp[MROWS * DMODEL];
__device__ float g_kp[MROWS * DMODEL];
__device__ float g_vp[MROWS * DMODEL];
__device__ float g_ao[MROWS * DMODEL];

// ===========================================================================
// PTX helpers (baseline compute_103-safe: mma.sync + cp.async only)
// ===========================================================================
__device__ __forceinline__ uint32_t smem_u32(const void* p) {
    uint32_t a;
    asm("{ .reg .u64 t; cvta.to.shared.u64 t, %1; cvt.u32.u64 %0, t; }"
        : "=r"(a) : "l"(p));
    return a;
}
#define CP_ASYNC16(smem, gptr)                                                 \
    asm volatile("cp.async.cg.shared.global [%0], [%1], 16;"                   \
                 :: "r"(smem), "l"(gptr))
#define CP_COMMIT() asm volatile("cp.async.commit_group;" ::: "memory")
#define CP_WAIT(n)  asm volatile("cp.async.wait_group %0;" :: "n"(n) : "memory")

__device__ __forceinline__ uint32_t f2tf32(float x) {
    uint32_t u;
    asm("cvt.rna.tf32.f32 %0, %1;" : "=r"(u) : "f"(x));
    return u;
}
// round a float4 to tf32 bit patterns, in place (values stay valid floats)
__device__ __forceinline__ float4 rnd4(float4 f) {
    return make_float4(__uint_as_float(f2tf32(f.x)), __uint_as_float(f2tf32(f.y)),
                       __uint_as_float(f2tf32(f.z)), __uint_as_float(f2tf32(f.w)));
}
__device__ __forceinline__ void mma_tf32(float& c0, float& c1, float& c2, float& c3,
                                         uint32_t a0, uint32_t a1, uint32_t a2, uint32_t a3,
                                         uint32_t b0, uint32_t b1) {
    asm volatile(
        "mma.sync.aligned.m16n8k8.row.col.f32.tf32.tf32.f32 "
        "{%0,%1,%2,%3}, {%4,%5,%6,%7}, {%8,%9}, {%0,%1,%2,%3};"
        : "+f"(c0), "+f"(c1), "+f"(c2), "+f"(c3)
        : "r"(a0), "r"(a1), "r"(a2), "r"(a3), "r"(b0), "r"(b1));
}

// Fast exp2: magic-number round-to-nearest + Taylor-6 on [-0.5, 0.5].
__device__ __forceinline__ float exp2m(float z) {
    z = fmaxf(z, -126.0f);
    float r = z + 12582912.0f;
    int   n = __float_as_int(r) - 0x4B400000;
    float f = z - (r - 12582912.0f);
    float p =              1.54035303933816e-4f;
    p = fmaf(p, f, 1.33335581464284e-3f);
    p = fmaf(p, f, 9.61812910762848e-3f);
    p = fmaf(p, f, 5.55041086648216e-2f);
    p = fmaf(p, f, 2.40226506959101e-1f);
    p = fmaf(p, f, 6.93147180559945e-1f);
    p = fmaf(p, f, 1.0f);
    return __int_as_float(__float_as_int(p) + (n << 23));
}
#define LOG2E 1.4426950408889634f

// ===========================================================================
// tf32 mma.sync GEMM:  C[M,1024] = A[M,1024] @ W[1024,1024]^T + bias
// 128x128 CTA tile, BK=32, 256 threads, double-buffered cp.async.
// NEW: operands rounded to tf32 ONCE in smem (each thread rounds the data it
// staged, right after wait_group — own-data, so no extra sync). The mma
// fragment loads are then raw uint32 loads with zero cvt in the hot loop.
// ===========================================================================
struct GemmJob { const float* A; const float* W; const float* bias; float* C; };
struct GemmParams { GemmJob job[3]; };

#define GBM 128
#define GBN 128
#define GBK 32
#define GNIT (DMODEL / GBK)
#define LDT 36
#define TILEF (128 * LDT)
#define SMEM_REQ (4 * TILEF * 4)

__global__ __launch_bounds__(256) void gemm_tf32(GemmParams p)
{
    extern __shared__ float dsm[];
    const uint32_t sa = smem_u32(dsm);

    const GemmJob j = p.job[blockIdx.z];
    const int bm = blockIdx.y * GBM;
    const int bn = blockIdx.x * GBN;
    const int tid = threadIdx.x;
    const int wid = tid >> 5;
    const int lid = tid & 31;
    const int wm = (wid >> 2) * 64;
    const int wn = (wid & 3) * 32;
    const int g = lid >> 2;
    const int t = lid & 3;

    const int row0 = tid >> 3;
    const int c4 = (tid & 7) * 4;
    const float* Ag[4];
    const float* Wg[4];
    uint32_t sAoff[4], sBoff[4];
#pragma unroll
    for (int jj = 0; jj < 4; jj++) {
        int row = row0 + jj * 32;
        Ag[jj] = j.A + (size_t)(bm + row) * DMODEL + c4;
        Wg[jj] = j.W + (size_t)(bn + row) * DMODEL + c4;
        sAoff[jj] = (uint32_t)((row * LDT + c4) * 4);
        sBoff[jj] = (uint32_t)((2 * TILEF + row * LDT + c4) * 4);
    }

#pragma unroll
    for (int jj = 0; jj < 4; jj++) {
        CP_ASYNC16(sa + sAoff[jj], Ag[jj]);
        CP_ASYNC16(sa + sBoff[jj], Wg[jj]);
    }
    CP_COMMIT();

    float acc[4][4][4];
#pragma unroll
    for (int mt = 0; mt < 4; mt++)
#pragma unroll
        for (int nt = 0; nt < 4; nt++)
#pragma unroll
            for (int r = 0; r < 4; r++) acc[mt][nt][r] = 0.f;

    for (int it = 0; it < GNIT; it++) {
        CP_WAIT(0);
        // round own staged data to tf32 in place (own cp.async data is
        // visible to this thread after wait_group; no cross-thread dep)
        {
            float* Abuf = dsm + (it & 1) * TILEF;
            float* Bbuf = dsm + 2 * TILEF + (it & 1) * TILEF;
#pragma unroll
            for (int jj = 0; jj < 4; jj++) {
                int row = row0 + jj * 32;
                float4* ap = (float4*)&Abuf[row * LDT + c4];
                float4* bp = (float4*)&Bbuf[row * LDT + c4];
                *ap = rnd4(*ap);
                *bp = rnd4(*bp);
            }
        }
        __syncthreads();

        if (it + 1 < GNIT) {
            const uint32_t dst = (uint32_t)(((it + 1) & 1) * TILEF * 4);
            const int koff = (it + 1) * GBK;
#pragma unroll
            for (int jj = 0; jj < 4; jj++) {
                CP_ASYNC16(sa + sAoff[jj] + dst, Ag[jj] + koff);
                CP_ASYNC16(sa + sBoff[jj] + dst, Wg[jj] + koff);
            }
            CP_COMMIT();
        }

        const uint32_t* Ab = (const uint32_t*)(dsm + (it & 1) * TILEF);
        const uint32_t* Bb = (const uint32_t*)(dsm + 2 * TILEF + (it & 1) * TILEF);

#pragma unroll
        for (int ks = 0; ks < 4; ks++) {
            const int kb = ks * 8;
            uint32_t bf[4][2];
#pragma unroll
            for (int nt = 0; nt < 4; nt++) {
                const uint32_t* bp = Bb + (wn + nt * 8 + g) * LDT + kb + t;
                bf[nt][0] = bp[0];
                bf[nt][1] = bp[4];
            }
#pragma unroll
            for (int mt = 0; mt < 4; mt++) {
                const uint32_t* ap = Ab + (wm + mt * 16 + g) * LDT + kb + t;
                uint32_t a0 = ap[0];
                uint32_t a1 = ap[8 * LDT];
                uint32_t a2 = ap[4];
                uint32_t a3 = ap[8 * LDT + 4];
#pragma unroll
                for (int nt = 0; nt < 4; nt++)
                    mma_tf32(acc[mt][nt][0], acc[mt][nt][1],
                             acc[mt][nt][2], acc[mt][nt][3],
                             a0, a1, a2, a3, bf[nt][0], bf[nt][1]);
            }
        }
        __syncthreads();
    }

#pragma unroll
    for (int mt = 0; mt < 4; mt++) {
        const int row = bm + wm + mt * 16 + g;
#pragma unroll
        for (int nt = 0; nt < 4; nt++) {
            const int col = bn + wn + nt * 8 + 2 * t;
            const float b0 = j.bias[col], b1 = j.bias[col + 1];
            float* c0p = j.C + (size_t)row * DMODEL + col;
            float* c1p = j.C + (size_t)(row + 8) * DMODEL + col;
            *(float2*)c0p = make_float2(acc[mt][nt][0] + b0, acc[mt][nt][1] + b1);
            *(float2*)c1p = make_float2(acc[mt][nt][2] + b0, acc[mt][nt][3] + b1);
        }
    }
}

// ===========================================================================
// Tensor-core flash attention v5:
//  - QK^T / PV single-pass tf32; P tf32-rounded and l accumulated from
//    rounded p (consistent weights)
//  - K/V rounded to tf32 ONCE per tile in smem (own-data after wait_group),
//    hot loops do raw uint loads, zero cvt
//  - cp.async double-buffered K/V, warp-local softmax, FMA exp2
// ===========================================================================
#define ALD 68
#define VLD 72
#define KBUF 4352
#define VBUF 4608
#define OFF_V  (2 * KBUF)
#define OFF_PB (2 * KBUF + 2 * VBUF)      // 17920
#define OFF_ST (OFF_PB + KBUF)            // 22272
#define ATT_SMEMF (OFF_ST + 192)
#define ATT_SMEMB (ATT_SMEMF * 4)

__global__ __launch_bounds__(128) void attn_mma()
{
    extern __shared__ float sm[];
    float* Pb   = sm + OFF_PB;
    float* mrow = sm + OFF_ST;
    float* lrow = sm + OFF_ST + 64;
    float* crow = sm + OFF_ST + 128;
    const uint32_t s0 = smem_u32(sm);

    const int tid = threadIdx.x;
    const int wid = tid >> 5;
    const int lid = tid & 31;
    const int g = lid >> 2;
    const int t = lid & 3;
    const int m0 = wid * 16;
    const int h = blockIdx.y;
    const int b = blockIdx.z;
    const int qbase = b * SEQ + blockIdx.x * 64;

    const float* qg = g_qp + (size_t)qbase * DMODEL + h * DK;
    const float* kg = g_kp + (size_t)b * SEQ * DMODEL + h * DK;
    const float* vg = g_vp + (size_t)b * SEQ * DMODEL + h * DK;

    const int rr = tid >> 4;
    const int cc = (tid & 15) << 2;

    // prefetch tile 0
#pragma unroll
    for (int i = 0; i < 8; i++) {
        int r = rr + i * 8;
        CP_ASYNC16(s0 + (uint32_t)((r * ALD + cc) * 4),
                   kg + (size_t)r * DMODEL + cc);
        CP_ASYNC16(s0 + (uint32_t)((OFF_V + r * VLD + cc) * 4),
                   vg + (size_t)r * DMODEL + cc);
    }
    CP_COMMIT();

    // stage Q into Pb, init stats
#pragma unroll
    for (int i = 0; i < 8; i++) {
        int r = rr + i * 8;
        *(float4*)&Pb[r * ALD + cc] = *(const float4*)(qg + (size_t)r * DMODEL + cc);
    }
    if (tid < 64) { mrow[tid] = -1e30f; lrow[tid] = 0.f; }
    __syncthreads();

    // preload scaled Q fragments (single-term, rna)
    uint32_t qb[8][4];
#pragma unroll
    for (int ks = 0; ks < 8; ks++) {
        int kb = ks * 8;
        qb[ks][0] = f2tf32(Pb[(m0 + g) * ALD + kb + t] * 0.125f);
        qb[ks][1] = f2tf32(Pb[(m0 + g + 8) * ALD + kb + t] * 0.125f);
        qb[ks][2] = f2tf32(Pb[(m0 + g) * ALD + kb + t + 4] * 0.125f);
        qb[ks][3] = f2tf32(Pb[(m0 + g + 8) * ALD + kb + t + 4] * 0.125f);
    }

    float Oa[8][4];
#pragma unroll
    for (int nt = 0; nt < 8; nt++)
#pragma unroll
        for (int r = 0; r < 4; r++) Oa[nt][r] = 0.f;

    const int NT = SEQ / 64;
    for (int tt = 0; tt < NT; tt++) {
        if (tt + 1 < NT) {
            const int buf = (tt + 1) & 1;
            const size_t gof = (size_t)(tt + 1) * 64 * DMODEL;
#pragma unroll
            for (int i = 0; i < 8; i++) {
                int r = rr + i * 8;
                CP_ASYNC16(s0 + (uint32_t)((buf * KBUF + r * ALD + cc) * 4),
                           kg + gof + (size_t)r * DMODEL + cc);
                CP_ASYNC16(s0 + (uint32_t)((OFF_V + buf * VBUF + r * VLD + cc) * 4),
                           vg + gof + (size_t)r * DMODEL + cc);
            }
            CP_COMMIT();
            CP_WAIT(1);
        } else {
            CP_WAIT(0);
        }
        // round own staged K/V data to tf32 in place (visible post-wait)
        {
            float* Kb = sm + (tt & 1) * KBUF;
            float* Vb = sm + OFF_V + (tt & 1) * VBUF;
#pragma unroll
            for (int i = 0; i < 8; i++) {
                int r = rr + i * 8;
                float4* kp = (float4*)&Kb[r * ALD + cc];
                float4* vp = (float4*)&Vb[r * VLD + cc];
                *kp = rnd4(*kp);
                *vp = rnd4(*vp);
            }
        }
        __syncthreads();

        const uint32_t* Kc = (const uint32_t*)(sm + (tt & 1) * KBUF);
        const uint32_t* Vc = (const uint32_t*)(sm + OFF_V + (tt & 1) * VBUF);

        // ---- QK^T single-pass (raw uint operand loads) ----
        float Sa[8][4];
#pragma unroll
        for (int nt = 0; nt < 8; nt++)
#pragma unroll
            for (int r = 0; r < 4; r++) Sa[nt][r] = 0.f;

#pragma unroll
        for (int ks = 0; ks < 8; ks++) {
            int kb = ks * 8;
#pragma unroll
            for (int nt = 0; nt < 8; nt++) {
                const uint32_t* bp = Kc + (nt * 8 + g) * ALD + kb + t;
                mma_tf32(Sa[nt][0], Sa[nt][1], Sa[nt][2], Sa[nt][3],
                         qb[ks][0], qb[ks][1], qb[ks][2], qb[ks][3],
                         bp[0], bp[4]);
            }
        }
#pragma unroll
        for (int nt = 0; nt < 8; nt++) {
            int ccol = nt * 8 + 2 * t;
            *(float2*)&Pb[(m0 + g) * ALD + ccol]     = make_float2(Sa[nt][0], Sa[nt][1]);
            *(float2*)&Pb[(m0 + g + 8) * ALD + ccol] = make_float2(Sa[nt][2], Sa[nt][3]);
        }
        __syncwarp();

        // ---- online softmax (warp-local rows, 2 threads/row) ----
        {
            int row = tid >> 1, half = tid & 1;
            float* Sr = Pb + row * ALD + half * 32;
            float4 s4[8];
            float mx = -1e30f;
#pragma unroll
            for (int i = 0; i < 8; i++) {
                s4[i] = ((float4*)Sr)[i];
                mx = fmaxf(mx, fmaxf(fmaxf(s4[i].x, s4[i].y), fmaxf(s4[i].z, s4[i].w)));
            }
            mx = fmaxf(mx, __shfl_xor_sync(0xffffffffu, mx, 1));
            float mold = mrow[row];
            float mnew = fmaxf(mold, mx);
            float ls = 0.f;
#pragma unroll
            for (int i = 0; i < 8; i++) {
                float px = __uint_as_float(f2tf32(exp2m((s4[i].x - mnew) * LOG2E)));
                float py = __uint_as_float(f2tf32(exp2m((s4[i].y - mnew) * LOG2E)));
                float pz = __uint_as_float(f2tf32(exp2m((s4[i].z - mnew) * LOG2E)));
                float pw = __uint_as_float(f2tf32(exp2m((s4[i].w - mnew) * LOG2E)));
                ls += (px + py) + (pz + pw);
                ((float4*)Sr)[i] = make_float4(px, py, pz, pw);
            }
            ls += __shfl_xor_sync(0xffffffffu, ls, 1);
            if (half == 0) {
                float cf = exp2m((mold - mnew) * LOG2E);
                mrow[row] = mnew;
                lrow[row] = lrow[row] * cf + ls;
                crow[row] = cf;
            }
        }
        __syncwarp();

        // ---- rescale O, then O += p'*v (single-pass, raw uint loads) ----
        {
            float c0 = crow[m0 + g], c1 = crow[m0 + g + 8];
#pragma unroll
            for (int nt = 0; nt < 8; nt++) {
                Oa[nt][0] *= c0; Oa[nt][1] *= c0;
                Oa[nt][2] *= c1; Oa[nt][3] *= c1;
            }
        }
        const uint32_t* Pu = (const uint32_t*)Pb;
#pragma unroll
        for (int ks = 0; ks < 8; ks++) {
            int kb = ks * 8;
            uint32_t pb0 = Pu[(m0 + g) * ALD + kb + t];
            uint32_t pb1 = Pu[(m0 + g + 8) * ALD + kb + t];
            uint32_t pb2 = Pu[(m0 + g) * ALD + kb + t + 4];
            uint32_t pb3 = Pu[(m0 + g + 8) * ALD + kb + t + 4];
#pragma unroll
            for (int nt = 0; nt < 8; nt++) {
                mma_tf32(Oa[nt][0], Oa[nt][1], Oa[nt][2], Oa[nt][3],
                         pb0, pb1, pb2, pb3,
                         Vc[(kb + t) * VLD + nt * 8 + g],
                         Vc[(kb + t + 4) * VLD + nt * 8 + g]);
            }
        }
        __syncthreads();
    }

    // epilogue
    float inv0 = 1.0f / lrow[m0 + g];
    float inv1 = 1.0f / lrow[m0 + g + 8];
    float* o0 = g_ao + (size_t)(qbase + m0 + g) * DMODEL + h * DK;
    float* o1 = g_ao + (size_t)(qbase + m0 + g + 8) * DMODEL + h * DK;
#pragma unroll
    for (int nt = 0; nt < 8; nt++) {
        int ccol = nt * 8 + 2 * t;
        *(float2*)(o0 + ccol) = make_float2(Oa[nt][0] * inv0, Oa[nt][1] * inv0);
        *(float2*)(o1 + ccol) = make_float2(Oa[nt][2] * inv1, Oa[nt][3] * inv1);
    }
}

// ===========================================================================
extern "C" void kernel_launch(void* const* d_in, const int* in_sizes, int n_in,
                              void* d_out, int out_size)
{
    const float* v  = (const float*)d_in[0];
    const float* k  = (const float*)d_in[1];
    const float* q  = (const float*)d_in[2];
    const float* Wv = (const float*)d_in[3];
    const float* bv = (const float*)d_in[4];
    const float* Wk = (const float*)d_in[5];
    const float* bk = (const float*)d_in[6];
    const float* Wq = (const float*)d_in[7];
    const float* bq = (const float*)d_in[8];
    const float* Wo = (const float*)d_in[9];
    const float* bo = (const float*)d_in[10];
    float* out = (float*)d_out;

    float *qp, *kp, *vp, *ao;
    cudaGetSymbolAddress((void**)&qp, g_qp);
    cudaGetSymbolAddress((void**)&kp, g_kp);
    cudaGetSymbolAddress((void**)&vp, g_vp);
    cudaGetSymbolAddress((void**)&ao, g_ao);

    static bool attr_set = false;
    if (!attr_set) {
        cudaFuncSetAttribute(gemm_tf32,
                             cudaFuncAttributeMaxDynamicSharedMemorySize, SMEM_REQ);
        cudaFuncSetAttribute(attn_mma,
                             cudaFuncAttributeMaxDynamicSharedMemorySize, ATT_SMEMB);
        attr_set = true;
    }

    GemmParams pin;
    pin.job[0] = { q, Wq, bq, qp };
    pin.job[1] = { k, Wk, bk, kp };
    pin.job[2] = { v, Wv, bv, vp };
    dim3 ggrid(DMODEL / GBN, MROWS / GBM, 3);   // (8, 32, 3)
    gemm_tf32<<<ggrid, 256, SMEM_REQ>>>(pin);

    dim3 attn_grid(SEQ / 64, NHEADS, BATCH);    // (32, 16, 2)
    attn_mma<<<attn_grid, 128, ATT_SMEMB>>>();

    GemmParams pout;
    pout.job[0] = { ao, Wo, bo, out };
    pout.job[1] = { ao, Wo, bo, out };
    pout.job[2] = { ao, Wo, bo, out };
    dim3 ogrid(DMODEL / GBN, MROWS / GBM, 1);   // (8, 32, 1)
    gemm_tf32<<<ogrid, 256, SMEM_REQ>>>(pout);
}